// round 15
// baseline (speedup 1.0000x reference)
#include <cuda_runtime.h>
#include <cuda_bf16.h>
#include <stdint.h>

#define D_MODEL 1024
#define INTER   1024
#define N_EXP   8
#define T_TOK   8192
#define MAX_TILES 208
#define MAX_ROWS  (MAX_TILES * 128)   // 26624

// ---------------- scratch (device globals: allocation-free) ----------------
__device__ __nv_bfloat16 g_xh[(size_t)T_TOK * 1024], g_xl[(size_t)T_TOK * 1024];
__device__ __nv_bfloat16 g_wh[27ull * 1024 * 1024],  g_wl[27ull * 1024 * 1024];
__device__ __nv_bfloat16 g_hh[(size_t)MAX_ROWS * 1024], g_hl[(size_t)MAX_ROWS * 1024];
__device__ float g_c2[(size_t)MAX_ROWS * D_MODEL];
__device__ int   g_srcTok[MAX_ROWS];
__device__ int   g_eid [T_TOK * 2];
__device__ float g_wgt [T_TOK * 2];
__device__ int   g_slot[T_TOK * 2];
__device__ int   g_tileExpert[MAX_TILES];
__device__ int   g_nTiles;
__device__ int   g_sharedBase;

// ---------------- helpers ----------------
__device__ __forceinline__ uint32_t smem_u32(const void* p) {
    uint32_t a;
    asm("{ .reg .u64 t; cvta.to.shared.u64 t, %1; cvt.u32.u64 %0, t; }" : "=r"(a) : "l"(p));
    return a;
}
__device__ __forceinline__ void ldsm4(uint32_t* r, uint32_t a) {
    asm volatile("ldmatrix.sync.aligned.m8n8.x4.shared.b16 {%0,%1,%2,%3}, [%4];"
                 : "=r"(r[0]), "=r"(r[1]), "=r"(r[2]), "=r"(r[3]) : "r"(a));
}
__device__ __forceinline__ void ldsm4t(uint32_t* r, uint32_t a) {
    asm volatile("ldmatrix.sync.aligned.m8n8.x4.trans.shared.b16 {%0,%1,%2,%3}, [%4];"
                 : "=r"(r[0]), "=r"(r[1]), "=r"(r[2]), "=r"(r[3]) : "r"(a));
}
__device__ __forceinline__ void mma16816(float* d, const uint32_t* a, const uint32_t* b) {
    asm volatile("mma.sync.aligned.m16n8k16.row.col.f32.bf16.bf16.f32 "
                 "{%0,%1,%2,%3}, {%4,%5,%6,%7}, {%8,%9}, {%0,%1,%2,%3};"
                 : "+f"(d[0]), "+f"(d[1]), "+f"(d[2]), "+f"(d[3])
                 : "r"(a[0]), "r"(a[1]), "r"(a[2]), "r"(a[3]), "r"(b[0]), "r"(b[1]));
}
__device__ __forceinline__ void cpa16(uint32_t dst, const void* src, uint32_t sz) {
    asm volatile("cp.async.cg.shared.global [%0], [%1], 16, %2;"
                 :: "r"(dst), "l"(src), "r"(sz) : "memory");
}
#define CP_COMMIT() asm volatile("cp.async.commit_group;" ::: "memory")
#define CP_WAIT0()  asm volatile("cp.async.wait_group 0;" ::: "memory")
#define CP_WAIT1()  asm volatile("cp.async.wait_group 1;" ::: "memory")

// split fp32x4 -> bf16 hi (8B) + bf16 lo (8B)
__device__ __forceinline__ void stHiLo(__nv_bfloat16* hp, __nv_bfloat16* lp, float4 v) {
    __nv_bfloat16 h0 = __float2bfloat16(v.x), h1 = __float2bfloat16(v.y),
                  h2 = __float2bfloat16(v.z), h3 = __float2bfloat16(v.w);
    float l0 = v.x - __bfloat162float(h0), l1 = v.y - __bfloat162float(h1),
          l2 = v.z - __bfloat162float(h2), l3 = v.w - __bfloat162float(h3);
    uint16_t u0 = *(uint16_t*)&h0, u1 = *(uint16_t*)&h1,
             u2 = *(uint16_t*)&h2, u3 = *(uint16_t*)&h3;
    uint2 hv = make_uint2((uint32_t)u0 | ((uint32_t)u1 << 16),
                          (uint32_t)u2 | ((uint32_t)u3 << 16));
    __nv_bfloat162 p0 = __floats2bfloat162_rn(l0, l1), p1 = __floats2bfloat162_rn(l2, l3);
    uint2 lv = make_uint2(*(uint32_t*)&p0, *(uint32_t*)&p1);
    *(uint2*)hp = hv;
    *(uint2*)lp = lv;
}
__device__ __forceinline__ void stHiLo2(__nv_bfloat16* hp, __nv_bfloat16* lp,
                                        float a, float b) {
    __nv_bfloat16 h0 = __float2bfloat16(a), h1 = __float2bfloat16(b);
    float l0 = a - __bfloat162float(h0), l1 = b - __bfloat162float(h1);
    uint16_t u0 = *(uint16_t*)&h0, u1 = *(uint16_t*)&h1;
    uint32_t hv = (uint32_t)u0 | ((uint32_t)u1 << 16);
    __nv_bfloat162 p = __floats2bfloat162_rn(l0, l1);
    *(uint32_t*)hp = hv;
    *(uint32_t*)lp = *(uint32_t*)&p;
}

// ---------------- 0a) weights fp32 -> bf16 hi/lo planes ----------------
__global__ void prep_w(const float* __restrict__ w1, const float* __restrict__ w3,
                       const float* __restrict__ w2, const float* __restrict__ sw1,
                       const float* __restrict__ sw3, const float* __restrict__ sw2) {
    int z = blockIdx.y;
    const float* src;
    if (z < 9)       src = (z < 8) ? w1 + (size_t)z * 1048576 : sw1;
    else if (z < 18) { int e = z - 9;  src = (e < 8) ? w3 + (size_t)e * 1048576 : sw3; }
    else             { int e = z - 18; src = (e < 8) ? w2 + (size_t)e * 1048576 : sw2; }
    size_t off = (size_t)blockIdx.x * 1024 + threadIdx.x * 4;
    float4 v = *(const float4*)(src + off);
    size_t o = (size_t)z * 1048576 + off;
    stHiLo(&g_wh[o], &g_wl[o], v);
}

// ---------------- 0b) x fp32 -> bf16 hi/lo ----------------
__global__ void prep_x(const float* __restrict__ x) {
    size_t off = (size_t)blockIdx.x * 1024 + threadIdx.x * 4;
    float4 v = *(const float4*)(x + off);
    stHiLo(&g_xh[off], &g_xl[off], v);
}

// ---------------- 1) gate (proven) ----------------
__global__ void gate_kernel(const float* __restrict__ x, const float* __restrict__ gw) {
    int warp = threadIdx.x >> 5, lane = threadIdx.x & 31;
    int t = blockIdx.x * 4 + warp;
    const float* xr = x + (size_t)t * D_MODEL;
    float xa[32];
#pragma unroll
    for (int i = 0; i < 32; i++) xa[i] = xr[lane + i * 32];
    float p[8];
#pragma unroll
    for (int e = 0; e < 8; e++) {
        const float* w = gw + e * D_MODEL;
        float s = 0.f;
#pragma unroll
        for (int i = 0; i < 32; i++) s += xa[i] * w[lane + i * 32];
#pragma unroll
        for (int off = 16; off > 0; off >>= 1) s += __shfl_xor_sync(0xffffffffu, s, off);
        p[e] = s;
    }
    float m = p[0];
#pragma unroll
    for (int e = 1; e < 8; e++) m = fmaxf(m, p[e]);
    float den = 0.f;
#pragma unroll
    for (int e = 0; e < 8; e++) { p[e] = __expf(p[e] - m); den += p[e]; }
    float inv = 1.f / den;
#pragma unroll
    for (int e = 0; e < 8; e++) p[e] *= inv;
    int i0 = 0;
#pragma unroll
    for (int e = 1; e < 8; e++) if (p[e] > p[i0]) i0 = e;
    int i1 = -1; float v1 = -1.f;
#pragma unroll
    for (int e = 0; e < 8; e++) if (e != i0 && p[e] > v1) { v1 = p[e]; i1 = e; }
    if (lane == 0) {
        g_eid[2 * t]     = i0; g_wgt[2 * t]     = p[i0];
        g_eid[2 * t + 1] = i1; g_wgt[2 * t + 1] = v1;
    }
}

// ---------------- 2) deterministic counting sort (proven) ----------------
__global__ void route_build() {
    __shared__ int warpsum[32][8];
    __shared__ int sExpBase[9];
    __shared__ int sExpCnt[8];
    int tid = threadIdx.x, lane = tid & 31, wid = tid >> 5;

    int lc[8];
#pragma unroll
    for (int e = 0; e < 8; e++) lc[e] = 0;
    int base = tid * 16;
    int eids[16];
#pragma unroll
    for (int j = 0; j < 16; j++) { int e = g_eid[base + j]; eids[j] = e; lc[e]++; }

    int incl[8];
#pragma unroll
    for (int e = 0; e < 8; e++) {
        int v = lc[e];
#pragma unroll
        for (int o = 1; o < 32; o <<= 1) {
            int n = __shfl_up_sync(0xffffffffu, v, o);
            if (lane >= o) v += n;
        }
        incl[e] = v;
        if (lane == 31) warpsum[wid][e] = v;
    }
    __syncthreads();
    if (tid < 256) {
        int e = tid >> 5, l = tid & 31;
        int v = warpsum[l][e];
#pragma unroll
        for (int o = 1; o < 32; o <<= 1) {
            int n = __shfl_up_sync(0xffffffffu, v, o);
            if (l >= o) v += n;
        }
        warpsum[l][e] = v;
    }
    __syncthreads();
    if (tid == 0) {
        int off = 0, nt = 0;
        for (int e = 0; e < 8; e++) {
            int c = warpsum[31][e];
            sExpBase[e] = off; sExpCnt[e] = c;
            int tiles = (c + 127) >> 7;
            for (int j = 0; j < tiles; j++) g_tileExpert[nt++] = e;
            off += tiles << 7;
        }
        sExpBase[8] = off;
        for (int j = 0; j < 64; j++) g_tileExpert[nt++] = 8;
        g_nTiles = nt;
        g_sharedBase = off;
    }
    __syncthreads();

    int run[8];
#pragma unroll
    for (int e = 0; e < 8; e++) {
        int pw = (wid == 0) ? 0 : warpsum[wid - 1][e];
        run[e] = sExpBase[e] + pw + (incl[e] - lc[e]);
    }
#pragma unroll
    for (int j = 0; j < 16; j++) {
        int e = eids[j];
        int pos = run[e]++;
        g_srcTok[pos] = (base + j) >> 1;
        g_slot[base + j] = pos;
    }
    for (int e = 0; e < 8; e++) {
        int s = sExpBase[e] + sExpCnt[e], en = sExpBase[e + 1];
        for (int p = s + tid; p < en; p += 1024) g_srcTok[p] = -1;
    }
    int sb = sExpBase[8];
    for (int t = tid; t < T_TOK; t += 1024) g_srcTok[sb + t] = t;
}

// ---------------- 3) fused GEMM1+3 + SwiGLU -> h (bf16 hi/lo) ----------------
// block 128(M) x 64(N) x Kc32, 256 thr, 8 warps (4m x 2n of 32x32), dual B (W1,W3)
// 2-stage cp.async; MMA reordered product-major (dep distance 4-8)
#define PAE 40    // A pitch elems (80B)
#define PBE 72    // B pitch elems (144B)
#define SMEM_G13 77824

__global__ __launch_bounds__(256, 2) void gemm13_swiglu(
    const float* __restrict__ b1, const float* __restrict__ b3,
    const float* __restrict__ sb1, const float* __restrict__ sb3)
{
    int tileId = blockIdx.y;
    if (tileId >= g_nTiles) return;
    extern __shared__ char sm[];
    uint32_t smb = smem_u32(sm);
    int tid = threadIdx.x, lane = tid & 31, warp = tid >> 5;
    int e = g_tileExpert[tileId];
    int rowBase = tileId << 7;
    int n0 = blockIdx.x << 6;

    const __nv_bfloat16* W1h = g_wh + (size_t)e * 1048576;
    const __nv_bfloat16* W1l = g_wl + (size_t)e * 1048576;
    const __nv_bfloat16* W3h = g_wh + (size_t)(9 + e) * 1048576;
    const __nv_bfloat16* W3l = g_wl + (size_t)(9 + e) * 1048576;
    const float* bi1 = (e < N_EXP) ? (b1 + e * 1024) : sb1;
    const float* bi3 = (e < N_EXP) ? (b3 + e * 1024) : sb3;

    int aplane = tid >> 7, arow = tid & 127;
    int tokA = g_srcTok[rowBase + arow];
    uint32_t aSz = (tokA >= 0) ? 16u : 0u;
    const __nv_bfloat16* aSrc =
        (aplane ? g_xl : g_xh) + (size_t)max(tokA, 0) * 1024;
    uint32_t aDst = smb + aplane * 20480 + arow * 80;

    int bmat = tid >> 7, bplane = (tid >> 6) & 1, brow = (tid & 63) >> 1, bseg = tid & 1;
    const __nv_bfloat16* bSrc =
        (bmat ? (bplane ? W3l : W3h) : (bplane ? W1l : W1h))
        + (size_t)brow * 1024 + n0 + bseg * 32;
    uint32_t bDst = smb + 40960 + (bmat * 2 + bplane) * 9216 + brow * 144 + bseg * 64;

    auto issue = [&](int c) {
        int s = c & 1;
        const __nv_bfloat16* ap = aSrc + c * 32;
        uint32_t da = aDst + s * 10240;
#pragma unroll
        for (int q = 0; q < 4; q++) cpa16(da + q * 16, ap + q * 8, aSz);
        const __nv_bfloat16* bp = bSrc + (size_t)c * 32 * 1024;
        uint32_t db = bDst + s * 4608;
#pragma unroll
        for (int q = 0; q < 4; q++) cpa16(db + q * 16, bp + q * 8, 16u);
        CP_COMMIT();
    };

    float acc1[2][4][4], acc3[2][4][4];
#pragma unroll
    for (int m = 0; m < 2; m++)
#pragma unroll
        for (int n = 0; n < 4; n++)
#pragma unroll
            for (int j = 0; j < 4; j++) { acc1[m][n][j] = 0.f; acc3[m][n][j] = 0.f; }

    int warpM = (warp >> 1) * 32, warpN = (warp & 1) * 32;
    int lr = lane & 15, lcol = (lane >> 4) * 8;

    issue(0);
    for (int c = 0; c < 32; c++) {
        CP_WAIT0();
        __syncthreads();
        if (c + 1 < 32) issue(c + 1);
        int s = c & 1;
        uint32_t AHs = smb + s * 10240, ALs = smb + 20480 + s * 10240;
        uint32_t B1Hs = smb + 40960 + s * 4608, B1Ls = smb + 50176 + s * 4608;
        uint32_t B3Hs = smb + 59392 + s * 4608, B3Ls = smb + 68608 + s * 4608;
#pragma unroll
        for (int ks = 0; ks < 2; ks++) {
            uint32_t ah[2][4], al[2][4];
#pragma unroll
            for (int m = 0; m < 2; m++) {
                uint32_t o = (uint32_t)((warpM + m * 16 + lr) * PAE + ks * 16 + lcol) * 2;
                ldsm4(ah[m], AHs + o);
                ldsm4(al[m], ALs + o);
            }
#pragma unroll
            for (int np = 0; np < 2; np++) {
                uint32_t o = (uint32_t)((ks * 16 + lr) * PBE + warpN + np * 16 + lcol) * 2;
                uint32_t b1h[4], b1l[4], b3h[4], b3l[4];
                ldsm4t(b1h, B1Hs + o);
                ldsm4t(b1l, B1Ls + o);
                ldsm4t(b3h, B3Hs + o);
                ldsm4t(b3l, B3Ls + o);
                // pass 1: hi*hi (8 independent MMAs)
#pragma unroll
                for (int m = 0; m < 2; m++) {
                    mma16816(acc1[m][2 * np],     ah[m], b1h);
                    mma16816(acc1[m][2 * np + 1], ah[m], b1h + 2);
                    mma16816(acc3[m][2 * np],     ah[m], b3h);
                    mma16816(acc3[m][2 * np + 1], ah[m], b3h + 2);
                }
                // pass 2: hi*lo
#pragma unroll
                for (int m = 0; m < 2; m++) {
                    mma16816(acc1[m][2 * np],     ah[m], b1l);
                    mma16816(acc1[m][2 * np + 1], ah[m], b1l + 2);
                    mma16816(acc3[m][2 * np],     ah[m], b3l);
                    mma16816(acc3[m][2 * np + 1], ah[m], b3l + 2);
                }
                // pass 3: lo*hi
#pragma unroll
                for (int m = 0; m < 2; m++) {
                    mma16816(acc1[m][2 * np],     al[m], b1h);
                    mma16816(acc1[m][2 * np + 1], al[m], b1h + 2);
                    mma16816(acc3[m][2 * np],     al[m], b3h);
                    mma16816(acc3[m][2 * np + 1], al[m], b3h + 2);
                }
            }
        }
    }

    // epilogue: SwiGLU, split to bf16 hi/lo, store h planes
    int g = lane >> 2, cc = (lane & 3) * 2;
#pragma unroll
    for (int m = 0; m < 2; m++) {
        int r0 = rowBase + warpM + m * 16 + g;
#pragma unroll
        for (int n = 0; n < 4; n++) {
            int col = n0 + warpN + n * 8 + cc;
            float b1v0 = bi1[col], b1v1 = bi1[col + 1];
            float b3v0 = bi3[col], b3v1 = bi3[col + 1];
#pragma unroll
            for (int hrow = 0; hrow < 2; hrow++) {
                int row = r0 + hrow * 8;
                float gv0 = acc1[m][n][2 * hrow]     + b1v0;
                float gv1 = acc1[m][n][2 * hrow + 1] + b1v1;
                float uv0 = acc3[m][n][2 * hrow]     + b3v0;
                float uv1 = acc3[m][n][2 * hrow + 1] + b3v1;
                float h0 = gv0 / (1.f + __expf(-gv0)) * uv0;
                float h1 = gv1 / (1.f + __expf(-gv1)) * uv1;
                size_t o = (size_t)row * 1024 + col;
                stHiLo2(&g_hh[o], &g_hl[o], h0, h1);
            }
        }
    }
}

// ---------------- 4) GEMM2: C2 = H @ W2 + b2 ----------------
// block 128(M) x 128(N) x Kc32, 256 thr, 8 warps (4m x 2n of 32x64)
// 3-stage cp.async pipeline (wait_group 1); MMA product-major
#define PB2E 136  // B pitch elems (272B)
// smem: AH 3x10240 @0, AL @30720, BH 3x8704 @61440, BL @87552 -> 113664
#define SMEM_G2 113664

__global__ __launch_bounds__(256, 2) void gemm2_k(
    const float* __restrict__ b2, const float* __restrict__ sb2)
{
    int tileId = blockIdx.y;
    if (tileId >= g_nTiles) return;
    extern __shared__ char sm[];
    uint32_t smb = smem_u32(sm);
    int tid = threadIdx.x, lane = tid & 31, warp = tid >> 5;
    int e = g_tileExpert[tileId];
    int rowBase = tileId << 7;
    int n0 = blockIdx.x << 7;

    const __nv_bfloat16* Wh = g_wh + (size_t)(18 + e) * 1048576;
    const __nv_bfloat16* Wl = g_wl + (size_t)(18 + e) * 1048576;
    const float* bi = (e < N_EXP) ? (b2 + e * 1024) : sb2;

    int aplane = tid >> 7, arow = tid & 127;
    const __nv_bfloat16* aSrc =
        (aplane ? g_hl : g_hh) + (size_t)(rowBase + arow) * 1024;
    uint32_t aDst = smb + aplane * 30720 + arow * 80;

    int bplane = tid >> 7, brow = (tid & 127) >> 2, bseg = tid & 3;
    const __nv_bfloat16* bSrc = (bplane ? Wl : Wh) + (size_t)brow * 1024 + n0 + bseg * 32;
    uint32_t bDst = smb + 61440 + bplane * 26112 + brow * 272 + bseg * 64;

    auto issue = [&](int c) {
        int s = c % 3;
        const __nv_bfloat16* ap = aSrc + c * 32;
        uint32_t da = aDst + s * 10240;
#pragma unroll
        for (int q = 0; q < 4; q++) cpa16(da + q * 16, ap + q * 8, 16u);
        const __nv_bfloat16* bp = bSrc + (size_t)c * 32 * 1024;
        uint32_t db = bDst + s * 8704;
#pragma unroll
        for (int q = 0; q < 4; q++) cpa16(db + q * 16, bp + q * 8, 16u);
        CP_COMMIT();
    };

    float acc[2][8][4];
#pragma unroll
    for (int m = 0; m < 2; m++)
#pragma unroll
        for (int n = 0; n < 8; n++)
#pragma unroll
            for (int j = 0; j < 4; j++) acc[m][n][j] = 0.f;

    int warpM = (warp >> 1) * 32, warpN = (warp & 1) * 64;
    int lr = lane & 15, lcol = (lane >> 4) * 8;

    issue(0);
    issue(1);
    for (int c = 0; c < 32; c++) {
        if (c >= 30) { CP_WAIT0(); } else { CP_WAIT1(); }
        __syncthreads();
        if (c + 2 < 32) issue(c + 2);
        int s = c % 3;
        uint32_t AHs = smb + s * 10240, ALs = smb + 30720 + s * 10240;
        uint32_t BHs = smb + 61440 + s * 8704, BLs = smb + 87552 + s * 8704;
#pragma unroll
        for (int ks = 0; ks < 2; ks++) {
            uint32_t ah[2][4], al[2][4];
#pragma unroll
            for (int m = 0; m < 2; m++) {
                uint32_t o = (uint32_t)((warpM + m * 16 + lr) * PAE + ks * 16 + lcol) * 2;
                ldsm4(ah[m], AHs + o);
                ldsm4(al[m], ALs + o);
            }
#pragma unroll
            for (int np = 0; np < 4; np++) {
                uint32_t o = (uint32_t)((ks * 16 + lr) * PB2E + warpN + np * 16 + lcol) * 2;
                uint32_t bh[4], bl[4];
                ldsm4t(bh, BHs + o);
                ldsm4t(bl, BLs + o);
                // pass 1: hi*hi (4 independent)
#pragma unroll
                for (int m = 0; m < 2; m++) {
                    mma16816(acc[m][2 * np],     ah[m], bh);
                    mma16816(acc[m][2 * np + 1], ah[m], bh + 2);
                }
                // pass 2: hi*lo
#pragma unroll
                for (int m = 0; m < 2; m++) {
                    mma16816(acc[m][2 * np],     ah[m], bl);
                    mma16816(acc[m][2 * np + 1], ah[m], bl + 2);
                }
                // pass 3: lo*hi
#pragma unroll
                for (int m = 0; m < 2; m++) {
                    mma16816(acc[m][2 * np],     al[m], bh);
                    mma16816(acc[m][2 * np + 1], al[m], bh + 2);
                }
            }
        }
    }

    int g = lane >> 2, cc = (lane & 3) * 2;
#pragma unroll
    for (int m = 0; m < 2; m++) {
        int r0 = rowBase + warpM + m * 16 + g;
        float* C0 = g_c2 + (size_t)r0 * 1024;
        float* C1 = C0 + 8 * 1024;
#pragma unroll
        for (int n = 0; n < 8; n++) {
            int col = n0 + warpN + n * 8 + cc;
            float bb0 = bi[col], bb1 = bi[col + 1];
            *(float2*)&C0[col] = make_float2(acc[m][n][0] + bb0, acc[m][n][1] + bb1);
            *(float2*)&C1[col] = make_float2(acc[m][n][2] + bb0, acc[m][n][3] + bb1);
        }
    }
}

// ---------------- 5) combine ----------------
__global__ void combine_kernel(float* __restrict__ out) {
    int t = blockIdx.x;
    int d4 = threadIdx.x;
    int s0 = g_slot[2 * t], s1 = g_slot[2 * t + 1];
    float w0 = g_wgt[2 * t], w1 = g_wgt[2 * t + 1];
    int sh = g_sharedBase + t;
    float4 c0 = *((const float4*)(g_c2 + (size_t)s0 * D_MODEL) + d4);
    float4 c1 = *((const float4*)(g_c2 + (size_t)s1 * D_MODEL) + d4);
    float4 cs = *((const float4*)(g_c2 + (size_t)sh * D_MODEL) + d4);
    float4 r;
    r.x = fmaf(w0, c0.x, fmaf(w1, c1.x, cs.x));
    r.y = fmaf(w0, c0.y, fmaf(w1, c1.y, cs.y));
    r.z = fmaf(w0, c0.z, fmaf(w1, c1.z, cs.z));
    r.w = fmaf(w0, c0.w, fmaf(w1, c1.w, cs.w));
    *((float4*)(out + (size_t)t * D_MODEL) + d4) = r;
}

// ---------------- launch ----------------
extern "C" void kernel_launch(void* const* d_in, const int* in_sizes, int n_in,
                              void* d_out, int out_size) {
    const float* x   = (const float*)d_in[0];
    const float* gw  = (const float*)d_in[1];
    const float* w1  = (const float*)d_in[2];
    const float* b1  = (const float*)d_in[3];
    const float* w2  = (const float*)d_in[4];
    const float* b2  = (const float*)d_in[5];
    const float* w3  = (const float*)d_in[6];
    const float* b3  = (const float*)d_in[7];
    const float* sw1 = (const float*)d_in[8];
    const float* sb1 = (const float*)d_in[9];
    const float* sw2 = (const float*)d_in[10];
    const float* sb2 = (const float*)d_in[11];
    const float* sw3 = (const float*)d_in[12];
    const float* sb3 = (const float*)d_in[13];
    float* out = (float*)d_out;

    cudaFuncSetAttribute(gemm13_swiglu, cudaFuncAttributeMaxDynamicSharedMemorySize, SMEM_G13);
    cudaFuncSetAttribute(gemm2_k,       cudaFuncAttributeMaxDynamicSharedMemorySize, SMEM_G2);

    prep_w<<<dim3(1024, 27), 256>>>(w1, w3, w2, sw1, sw3, sw2);
    prep_x<<<T_TOK, 256>>>(x);
    gate_kernel<<<T_TOK / 4, 128>>>(x, gw);
    route_build<<<1, 1024>>>();
    gemm13_swiglu<<<dim3(16, MAX_TILES), 256, SMEM_G13>>>(b1, b3, sb1, sb3);
    gemm2_k<<<dim3(8, MAX_TILES), 256, SMEM_G2>>>(b2, sb2);
    combine_kernel<<<T_TOK, 256>>>(out);
}